// round 15
// baseline (speedup 1.0000x reference)
#include <cuda_runtime.h>
#include <cuda_fp16.h>
#include <cstdint>

// W4 group-quant GEMM via mma.sync.m16n8k16.f16 (fp32 accum), base sm_103 PTX.
// out[M,N] = x[M,K] @ dequant(qweight)[K,N] + bias
// R10 = R9 + (a) B qweight prefetch 2 tiles deep (was 1; LDG latency exposed),
//            (b) PRMT+LOP3 nibble dequant (2 ops/pair vs ~6).
// 2 CTAs/SM: 256 thr / 8 warps (4M x 2N), BM=128, BN=128, BK=32.

#define THREADS 256
#define BM 128
#define BN 128
#define BK 32
#define BROW 136                     // B smem row stride (u32) per k-pair row
#define A_STG_U32 2048               // 8KB per A stage (16 slabs x 128 u32)
#define B_STG_U32 (16 * BROW)        // 2176 u32
#define TAB_OFF (4 * A_STG_U32 + 2 * B_STG_U32)   // 12544
#define SMEM_U32 (TAB_OFF + 512)
#define SMEM_BYTES (SMEM_U32 * 4)    // 52224

#define MAX_MK (4096 * 4096)
__device__ uint32_t g_xa[MAX_MK / 2];   // x as fp16 fragments (32MB)

#define CP_ASYNC16(dst, src) \
    asm volatile("cp.async.ca.shared.global [%0], [%1], 16;" :: "r"(dst), "l"(src))
#define CP_COMMIT() asm volatile("cp.async.commit_group;" ::: "memory")
#define CP_WAIT(N)  asm volatile("cp.async.wait_group %0;" :: "n"(N) : "memory")

__device__ __forceinline__ uint32_t h2u(__half2 h) { return *reinterpret_cast<uint32_t*>(&h); }
__device__ __forceinline__ __half2 u2h(uint32_t u) { return *reinterpret_cast<__half2*>(&u); }

__device__ __forceinline__ void mma_f16(float& c0, float& c1, float& c2, float& c3,
                                        uint32_t a0, uint32_t a1, uint32_t a2, uint32_t a3,
                                        uint32_t b0, uint32_t b1) {
    asm volatile(
        "mma.sync.aligned.m16n8k16.row.col.f32.f16.f16.f32 "
        "{%0,%1,%2,%3}, {%4,%5,%6,%7}, {%8,%9}, {%0,%1,%2,%3};"
        : "+f"(c0), "+f"(c1), "+f"(c2), "+f"(c3)
        : "r"(a0), "r"(a1), "r"(a2), "r"(a3), "r"(b0), "r"(b1));
}

// ---- prep: warp per 16m x 16k slab. lane(g,t): a0=(g,2t..2t+1), a1=(g+8,..),
// a2=(g,2t+8..), a3=(g+8,2t+8..). fp32 -> fp16(rn).
__global__ __launch_bounds__(128)
void xprep_kernel(const float* __restrict__ x, int M, int K)
{
    const int KS = K >> 4;
    const int slab = blockIdx.x * 4 + (threadIdx.x >> 5);
    const int lane = threadIdx.x & 31;
    const int mB = slab / KS;
    const int kB = slab - mB * KS;
    const int g = lane >> 2, t = lane & 3;
    const float* src = x + (size_t)(mB * 16 + g) * K + kB * 16 + 2 * t;
    float2 p00 = *(const float2*)(src);
    float2 p10 = *(const float2*)(src + (size_t)8 * K);
    float2 p01 = *(const float2*)(src + 8);
    float2 p11 = *(const float2*)(src + (size_t)8 * K + 8);
    uint4 v;
    v.x = h2u(__float22half2_rn(p00));
    v.y = h2u(__float22half2_rn(p10));
    v.z = h2u(__float22half2_rn(p01));
    v.w = h2u(__float22half2_rn(p11));
    *(uint4*)(g_xa + (size_t)slab * 128 + lane * 4) = v;
}

__global__ __launch_bounds__(THREADS, 2)
void wq4_mma_kernel(const int*   __restrict__ qw,
                    const int*   __restrict__ zeros,
                    const float* __restrict__ scales,
                    const float* __restrict__ bias,
                    float* __restrict__ out,
                    int M, int K, int N)
{
    extern __shared__ uint32_t sm[];
    uint32_t* As = sm;                         // 4 stages x 2048 u32
    uint32_t* Bs = sm + 4 * A_STG_U32;         // 2 stages x 2176 u32
    uint32_t* tS = sm + TAB_OFF;               // [2][128] half2-dup scales
    uint32_t* tZ = tS + 256;                   // [2][128] half2 zero-points

    const int tid  = threadIdx.x;
    const int wid  = tid >> 5;
    const int lane = tid & 31;
    const int g    = lane >> 2;
    const int t    = lane & 3;

    const int n0 = blockIdx.x * BN;
    const int m0 = blockIdx.y * BM;
    const int nq = N >> 3;
    const int NT = K / BK;                     // 128
    const int NG = K >> 7;                     // 32 groups

    // ---- A cp.async: 2 x 16B per thread per stage ----
    const int KSLAB = K >> 4;
    const int ci0 = tid, ci1 = tid + 256;
    const uint32_t* aSrc0 = g_xa + ((size_t)((m0 >> 4) + ((ci0 >> 5) >> 1)) * KSLAB
                            + ((ci0 >> 5) & 1)) * 128 + (ci0 & 31) * 4;
    const uint32_t* aSrc1 = g_xa + ((size_t)((m0 >> 4) + ((ci1 >> 5) >> 1)) * KSLAB
                            + ((ci1 >> 5) & 1)) * 128 + (ci1 & 31) * 4;
    const uint32_t aDst0 = (uint32_t)__cvta_generic_to_shared(As) + (uint32_t)ci0 * 16;
    const uint32_t aDst1 = (uint32_t)__cvta_generic_to_shared(As) + (uint32_t)ci1 * 16;

    // ---- B: kp = tid>>4 (16 k-pair rows), w = tid&15 (8 n each) ----
    const int kp = tid >> 4, w = tid & 15;
    const int* qP = qw + (size_t)(2 * kp) * nq + (n0 >> 3) + w;
    const int wsw = w & 4;                     // XOR swizzle selector
    uint32_t* bDst = Bs + kp * BROW + w * 8;

    float acc[2][8][4];
#pragma unroll
    for (int i = 0; i < 2; i++)
#pragma unroll
        for (int j = 0; j < 8; j++)
#pragma unroll
            for (int r = 0; r < 4; r++) acc[i][j][r] = 0.f;

    // ---- prologue: tables for groups 0,1 ----
    if (tid < 128) {
#pragma unroll
        for (int gg = 0; gg < 2; gg++) {
            float s = scales[(size_t)gg * N + n0 + tid];
            int   z = zeros[(size_t)gg * N + n0 + tid];
            tS[gg * 128 + tid] = h2u(__half2half2(__float2half_rn(s)));
            tZ[gg * 128 + tid] = 0x64006400u | (uint32_t)z | ((uint32_t)z << 16);
        }
    }

    // issue A tiles 0,1
    CP_ASYNC16(aDst0, aSrc0);
    CP_ASYNC16(aDst1, aSrc1);
    CP_COMMIT();
    CP_ASYNC16(aDst0 + A_STG_U32 * 4, aSrc0 + 256);
    CP_ASYNC16(aDst1 + A_STG_U32 * 4, aSrc1 + 256);
    CP_COMMIT();

    __syncthreads();   // tables visible

    // ---- B qweight registers: 2-deep prefetch ----
    int b0a = qP[0],                     b0b = qP[nq];
    int b1a = qP[(size_t)32 * nq],       b1b = qP[(size_t)32 * nq + nq];
    int b2a = 0, b2b = 0;
    float sf_next = 0.f; int zi_next = 0;
    uint32_t s2[8], zp2[8];

    for (int kt = 0; kt < NT; kt++) {
        // ---- prefetch A(kt+2), B(kt+2), table LDG ----
        if (kt < NT - 2) {
            const uint32_t so = (uint32_t)((kt + 2) & 3) * (A_STG_U32 * 4);
            const size_t go = (size_t)(kt + 2) * 256;
            CP_ASYNC16(aDst0 + so, aSrc0 + go);
            CP_ASYNC16(aDst1 + so, aSrc1 + go);
            CP_COMMIT();
            const int* qn = qP + (size_t)(kt + 2) * 32 * nq;
            b2a = qn[0]; b2b = qn[nq];
        }
        if ((kt & 3) == 2 && tid < 128) {
            const int gL = (kt >> 2) + 2;
            if (gL < NG) {
                sf_next = scales[(size_t)gL * N + n0 + tid];
                zi_next = zeros[(size_t)gL * N + n0 + tid];
            }
        }

        if (kt < NT - 2)       { CP_WAIT(2); }
        else if (kt == NT - 2) { CP_WAIT(1); }
        else                   { CP_WAIT(0); }

        if ((kt & 3) == 0) {
            const int gC = kt >> 2;
            const int tb = (gC & 1) * 128 + w * 8;
            uint4 sA = *(uint4*)(tS + tb); uint4 sB = *(uint4*)(tS + tb + 4);
            uint4 zA = *(uint4*)(tZ + tb); uint4 zB = *(uint4*)(tZ + tb + 4);
            s2[0]=sA.x; s2[1]=sA.y; s2[2]=sA.z; s2[3]=sA.w;
            s2[4]=sB.x; s2[5]=sB.y; s2[6]=sB.z; s2[7]=sB.w;
            zp2[0]=zA.x; zp2[1]=zA.y; zp2[2]=zA.z; zp2[3]=zA.w;
            zp2[4]=zB.x; zp2[5]=zB.y; zp2[6]=zB.z; zp2[7]=zB.w;
            if (kt >= 4 && tid < 128) {
                const int gS = gC + 1;
                if (gS < NG) {
                    tS[(gS & 1) * 128 + tid] = h2u(__half2half2(__float2half_rn(sf_next)));
                    tZ[(gS & 1) * 128 + tid] =
                        0x64006400u | (uint32_t)zi_next | ((uint32_t)zi_next << 16);
                }
            }
        }

        // ---- dequant B(kt): PRMT interleave + LOP3 extract, 8 half2 ----
        {
            const uint32_t w0 = (uint32_t)b0a, w1 = (uint32_t)b0b;
            // c1: n1n0 | n3n2 | m1m0 | m3m2  (n = w0 nibbles, m = w1 nibbles)
            const uint32_t c1 = __byte_perm(w0, w1, 0x5410);
            const uint32_t c2 = __byte_perm(w0, w1, 0x7632);
            uint32_t q[8];
            q[0] = (c1         & 0x000F000Fu) | 0x64006400u;
            q[1] = ((c1 >> 4)  & 0x000F000Fu) | 0x64006400u;
            q[2] = ((c1 >> 8)  & 0x000F000Fu) | 0x64006400u;
            q[3] = ((c1 >> 12) & 0x000F000Fu) | 0x64006400u;
            q[4] = (c2         & 0x000F000Fu) | 0x64006400u;
            q[5] = ((c2 >> 4)  & 0x000F000Fu) | 0x64006400u;
            q[6] = ((c2 >> 8)  & 0x000F000Fu) | 0x64006400u;
            q[7] = ((c2 >> 12) & 0x000F000Fu) | 0x64006400u;
#pragma unroll
            for (int j = 0; j < 8; j++)
                q[j] = h2u(__hmul2(__hsub2(u2h(q[j]), u2h(zp2[j])), u2h(s2[j])));
            uint32_t* dst = bDst + (kt & 1) * B_STG_U32;
            *(uint4*)(dst + wsw)       = make_uint4(q[0], q[1], q[2], q[3]);
            *(uint4*)(dst + (wsw ^ 4)) = make_uint4(q[4], q[5], q[6], q[7]);
        }

        __syncthreads();

        // ---- compute: 2 ks-steps of m16n8k16, warp tile 32m x 64n ----
        const uint32_t* Ast = As + (kt & 3) * A_STG_U32;
        const uint32_t* Bst = Bs + (kt & 1) * B_STG_U32;
#pragma unroll
        for (int ks = 0; ks < 2; ks++) {
            uint32_t aF[2][4];
#pragma unroll
            for (int mt = 0; mt < 2; mt++) {
                uint4 v = *(const uint4*)(Ast + ((((wid & 3) * 2 + mt) * 2 + ks) * 128)
                                          + lane * 4);
                aF[mt][0] = v.x; aF[mt][1] = v.y; aF[mt][2] = v.z; aF[mt][3] = v.w;
            }
            const int row0 = ks * 8 + t;
#pragma unroll
            for (int nt = 0; nt < 8; nt++) {
                const int b = (wid >> 2) * 8 + nt;          // n-block (0..15)
                const int offn = b * 8 + (g ^ (b & 4));     // XOR swizzle
                uint32_t b0 = Bst[row0 * BROW + offn];
                uint32_t b1 = Bst[(row0 + 4) * BROW + offn];
#pragma unroll
                for (int mt = 0; mt < 2; mt++)
                    mma_f16(acc[mt][nt][0], acc[mt][nt][1],
                            acc[mt][nt][2], acc[mt][nt][3],
                            aF[mt][0], aF[mt][1], aF[mt][2], aF[mt][3], b0, b1);
            }
        }

        b0a = b1a; b0b = b1b;
        b1a = b2a; b1b = b2b;
    }

    // ---- epilogue ----
    const int mwarp = (wid & 3) * 32;
    const int nwarp = (wid >> 2) * 64;
#pragma unroll
    for (int nt = 0; nt < 8; nt++) {
        const int col = n0 + nwarp + nt * 8 + 2 * t;
        const float2 bb = *(const float2*)(bias + col);
#pragma unroll
        for (int mt = 0; mt < 2; mt++) {
            const int row0 = m0 + mwarp + mt * 16 + g;
            *(float2*)(out + (size_t)row0 * N + col) =
                make_float2(acc[mt][nt][0] + bb.x, acc[mt][nt][1] + bb.y);
            *(float2*)(out + (size_t)(row0 + 8) * N + col) =
                make_float2(acc[mt][nt][2] + bb.x, acc[mt][nt][3] + bb.y);
        }
    }
}

extern "C" void kernel_launch(void* const* d_in, const int* in_sizes, int n_in,
                              void* d_out, int out_size)
{
    const float* x      = (const float*)d_in[0];
    const int*   qw     = (const int*)d_in[1];
    const int*   zeros  = (const int*)d_in[2];
    const float* scales = (const float*)d_in[3];
    const float* bias   = (const float*)d_in[4];
    float* out = (float*)d_out;

    const int N = in_sizes[4];                                   // 11008
    const int K = (int)(((long long)in_sizes[1] * 8) / N);       // 4096
    const int M = in_sizes[0] / K;                               // 4096

    const int slabs = (M / 16) * (K / 16);
    xprep_kernel<<<slabs / 4, 128>>>(x, M, K);

    cudaFuncSetAttribute(wq4_mma_kernel,
                         cudaFuncAttributeMaxDynamicSharedMemorySize, SMEM_BYTES);
    dim3 grid(N / BN, M / BM);
    wq4_mma_kernel<<<grid, THREADS, SMEM_BYTES>>>(qw, zeros, scales, bias, out, M, K, N);
}